// round 9
// baseline (speedup 1.0000x reference)
#include <cuda_runtime.h>
#include <cuda_fp16.h>
#include <cstdint>

#define NN     100000
#define EE     1600000
#define DIN    256
#define DOUT   64
#define ALPHA  0.2f

// ---------------- scratch ---------------------------------------------------
__device__ float d_Xp[(size_t)NN * DOUT];      // 25.6 MB  X @ W  (fp32)
__device__ float d_s0[NN];
__device__ float d_s1[NN];
__device__ float d_att[EE];                    // leakyrelu'd scores (pre-exp)
__device__ int   d_rowptr[NN + 1];
__device__ unsigned int d_gminkey;             // monotone-encoded float min
__device__ unsigned int d_gmaxkey;

// ---------------- monotone float<->uint encode ------------------------------
__device__ __forceinline__ unsigned int fenc(float f) {
    unsigned int u = __float_as_uint(f);
    return u ^ ((unsigned int)((int)u >> 31) | 0x80000000u);
}
__device__ __forceinline__ float fdec(unsigned int k) {
    unsigned int u = k ^ ((unsigned int)((int)(~k) >> 31) | 0x80000000u);
    return __uint_as_float(u);
}

// ---------------- fp16 helpers ----------------------------------------------
__device__ __forceinline__ uint32_t packh2(float a, float b) {
    __half2 h = __floats2half2_rn(a, b);      // a -> low half
    return *(uint32_t*)&h;
}

// mma.sync m16n8k16 fp16: D += A * B (A row-major 16x16, B col-major 16x8)
__device__ __forceinline__ void mma_fp16(float* d,
                                         uint32_t a0, uint32_t a1,
                                         uint32_t a2, uint32_t a3,
                                         uint32_t b0, uint32_t b1) {
    asm volatile(
        "mma.sync.aligned.m16n8k16.row.col.f32.f16.f16.f32 "
        "{%0,%1,%2,%3}, {%4,%5,%6,%7}, {%8,%9}, {%0,%1,%2,%3};"
        : "+f"(d[0]), "+f"(d[1]), "+f"(d[2]), "+f"(d[3])
        : "r"(a0), "r"(a1), "r"(a2), "r"(a3), "r"(b0), "r"(b1));
}

// ---------------- 1) fp16 single-pass tensor GEMM + fused scores ------------
#define BST2 132   // uint32 words per n-col (128 kpairs + 4 pad)

__global__ void __launch_bounds__(256, 2)
gemm_mma_kernel(const float* __restrict__ X, const float* __restrict__ W,
                const float* __restrict__ va0, const float* __restrict__ va1,
                int nrows) {
    __shared__ uint32_t Bs[DOUT * BST2];      // 33.8 KB  W^T fp16x2, full K

    const int tid  = threadIdx.x;
    const int wid  = tid >> 5;
    const int lane = tid & 31;
    const int g    = lane >> 2;
    const int t    = lane & 3;

    for (int idx = tid; idx < DOUT * (DIN / 2); idx += 256) {
        int n  = idx & 63;
        int kp = idx >> 6;
        int k  = kp * 2;
        Bs[n * BST2 + kp] = packh2(W[(size_t)k * DOUT + n],
                                   W[(size_t)(k + 1) * DOUT + n]);
    }

    const int m0 = blockIdx.x * 256 + wid * 32;
    const int r0 = m0 + g, r1 = m0 + g + 8, r2 = m0 + g + 16, r3 = m0 + g + 24;
    const bool v0 = r0 < nrows, v1 = r1 < nrows, v2 = r2 < nrows, v3 = r3 < nrows;
    const float* x0 = X + (size_t)r0 * DIN;
    const float* x1 = X + (size_t)r1 * DIN;
    const float* x2 = X + (size_t)r2 * DIN;
    const float* x3 = X + (size_t)r3 * DIN;

    float acc[2][8][4];
#pragma unroll
    for (int mt = 0; mt < 2; mt++)
#pragma unroll
        for (int nt = 0; nt < 8; nt++)
#pragma unroll
            for (int q = 0; q < 4; q++) acc[mt][nt][q] = 0.f;

    auto loadA = [&](float2* d, int s) {
        const int ks = s * 16;
        d[0] = v0 ? *(const float2*)(x0 + ks + 2 * t)     : make_float2(0.f, 0.f);
        d[1] = v1 ? *(const float2*)(x1 + ks + 2 * t)     : make_float2(0.f, 0.f);
        d[2] = v0 ? *(const float2*)(x0 + ks + 2 * t + 8) : make_float2(0.f, 0.f);
        d[3] = v1 ? *(const float2*)(x1 + ks + 2 * t + 8) : make_float2(0.f, 0.f);
        d[4] = v2 ? *(const float2*)(x2 + ks + 2 * t)     : make_float2(0.f, 0.f);
        d[5] = v3 ? *(const float2*)(x3 + ks + 2 * t)     : make_float2(0.f, 0.f);
        d[6] = v2 ? *(const float2*)(x2 + ks + 2 * t + 8) : make_float2(0.f, 0.f);
        d[7] = v3 ? *(const float2*)(x3 + ks + 2 * t + 8) : make_float2(0.f, 0.f);
    };
    auto compute = [&](const float2* d, int s) {
        uint32_t ah[2][4];
#pragma unroll
        for (int i = 0; i < 8; i++)
            ah[i >> 2][i & 3] = packh2(d[i].x, d[i].y);
        const int kp0 = s * 8;
#pragma unroll
        for (int nt = 0; nt < 8; nt++) {
            const int nb = (nt * 8 + g) * BST2 + kp0 + t;
            uint32_t b0 = Bs[nb], b1 = Bs[nb + 4];
#pragma unroll
            for (int mt = 0; mt < 2; mt++)
                mma_fp16(acc[mt][nt], ah[mt][0], ah[mt][1], ah[mt][2], ah[mt][3], b0, b1);
        }
    };

    float2 bufA[8], bufB[8];
    loadA(bufA, 0);
    __syncthreads();          // B smem ready

#pragma unroll 1
    for (int s = 0; s < 16; s += 2) {
        if (s + 1 < 16) loadA(bufB, s + 1);
        compute(bufA, s);
        if (s + 2 < 16) loadA(bufA, s + 2);
        if (s + 1 < 16) compute(bufB, s + 1);
    }

    // ---- epilogue: fp32 Xp store + fused s0/s1 ----
    float p0[2][2] = {{0.f, 0.f}, {0.f, 0.f}};
    float p1[2][2] = {{0.f, 0.f}, {0.f, 0.f}};
#pragma unroll
    for (int nt = 0; nt < 8; nt++) {
        float2 c0 = *(const float2*)&va0[nt * 8 + t * 2];
        float2 c1 = *(const float2*)&va1[nt * 8 + t * 2];
#pragma unroll
        for (int mt = 0; mt < 2; mt++) {
            p0[mt][0] += acc[mt][nt][0] * c0.x + acc[mt][nt][1] * c0.y;
            p0[mt][1] += acc[mt][nt][2] * c0.x + acc[mt][nt][3] * c0.y;
            p1[mt][0] += acc[mt][nt][0] * c1.x + acc[mt][nt][1] * c1.y;
            p1[mt][1] += acc[mt][nt][2] * c1.x + acc[mt][nt][3] * c1.y;
        }
    }
#pragma unroll
    for (int mt = 0; mt < 2; mt++)
#pragma unroll
        for (int hb = 0; hb < 2; hb++) {
            p0[mt][hb] += __shfl_xor_sync(0xFFFFFFFFu, p0[mt][hb], 1);
            p0[mt][hb] += __shfl_xor_sync(0xFFFFFFFFu, p0[mt][hb], 2);
            p1[mt][hb] += __shfl_xor_sync(0xFFFFFFFFu, p1[mt][hb], 1);
            p1[mt][hb] += __shfl_xor_sync(0xFFFFFFFFu, p1[mt][hb], 2);
        }

#pragma unroll
    for (int mt = 0; mt < 2; mt++) {
        int rowA = m0 + mt * 16 + g;
        int rowB = rowA + 8;
#pragma unroll
        for (int nt = 0; nt < 8; nt++) {
            int col = nt * 8 + t * 2;
            if (rowA < nrows)
                *(float2*)&d_Xp[(size_t)rowA * DOUT + col] =
                    make_float2(acc[mt][nt][0], acc[mt][nt][1]);
            if (rowB < nrows)
                *(float2*)&d_Xp[(size_t)rowB * DOUT + col] =
                    make_float2(acc[mt][nt][2], acc[mt][nt][3]);
        }
        if (t == 0) {
            if (rowA < nrows) { d_s0[rowA] = p0[mt][0]; d_s1[rowA] = p1[mt][0]; }
            if (rowB < nrows) { d_s0[rowB] = p0[mt][1]; d_s1[rowB] = p1[mt][1]; }
        }
    }
}

// ---------------- 2) row_ptr from sorted row_index + key init ---------------
__global__ void rowptr_kernel(const int* __restrict__ ri, int nrows, int ne) {
    if (blockIdx.x == 0 && threadIdx.x == 0) {
        d_gminkey = 0xFFFFFFFFu;
        d_gmaxkey = 0u;
    }
    int r = blockIdx.x * blockDim.x + threadIdx.x;
    if (r > nrows) return;
    int lo = 0, hi = ne;
    while (lo < hi) {
        int mid = (lo + hi) >> 1;
        if (ri[mid] < r) lo = mid + 1; else hi = mid;
    }
    d_rowptr[r] = lo;
}

// ---------------- 3) SDDMM + LeakyReLU + atomic min/max (8 edges/thread) ----
__global__ void __launch_bounds__(256) edge_kernel(const int* __restrict__ ri,
                                                   const int* __restrict__ ci,
                                                   int ne) {
    const int ne8  = ne >> 3;
    const int tail = ne - ne8 * 8;
    const int i    = blockIdx.x * blockDim.x + threadIdx.x;

    float lmin = 3.4e38f, lmax = -3.4e38f;
    if (i < ne8) {
        int4 ra = *(const int4*)&ri[(size_t)i * 8];
        int4 rb = *(const int4*)&ri[(size_t)i * 8 + 4];
        int4 ca = *(const int4*)&ci[(size_t)i * 8];
        int4 cb = *(const int4*)&ci[(size_t)i * 8 + 4];
        float v0 = d_s0[ra.x] + d_s1[ca.x];
        float v1 = d_s0[ra.y] + d_s1[ca.y];
        float v2 = d_s0[ra.z] + d_s1[ca.z];
        float v3 = d_s0[ra.w] + d_s1[ca.w];
        float v4 = d_s0[rb.x] + d_s1[cb.x];
        float v5 = d_s0[rb.y] + d_s1[cb.y];
        float v6 = d_s0[rb.z] + d_s1[cb.z];
        float v7 = d_s0[rb.w] + d_s1[cb.w];
        v0 = v0 > 0.f ? v0 : ALPHA * v0;
        v1 = v1 > 0.f ? v1 : ALPHA * v1;
        v2 = v2 > 0.f ? v2 : ALPHA * v2;
        v3 = v3 > 0.f ? v3 : ALPHA * v3;
        v4 = v4 > 0.f ? v4 : ALPHA * v4;
        v5 = v5 > 0.f ? v5 : ALPHA * v5;
        v6 = v6 > 0.f ? v6 : ALPHA * v6;
        v7 = v7 > 0.f ? v7 : ALPHA * v7;
        *(float4*)&d_att[(size_t)i * 8]     = make_float4(v0, v1, v2, v3);
        *(float4*)&d_att[(size_t)i * 8 + 4] = make_float4(v4, v5, v6, v7);
        lmin = fminf(fminf(fminf(v0, v1), fminf(v2, v3)),
                     fminf(fminf(v4, v5), fminf(v6, v7)));
        lmax = fmaxf(fmaxf(fmaxf(v0, v1), fmaxf(v2, v3)),
                     fmaxf(fmaxf(v4, v5), fmaxf(v6, v7)));
    } else if (i - ne8 < tail) {
        int e = ne8 * 8 + (i - ne8);
        float v = d_s0[ri[e]] + d_s1[ci[e]];
        v = v > 0.f ? v : ALPHA * v;
        d_att[e] = v;
        lmin = v; lmax = v;
    }
#pragma unroll
    for (int o = 16; o; o >>= 1) {
        lmin = fminf(lmin, __shfl_xor_sync(0xFFFFFFFFu, lmin, o));
        lmax = fmaxf(lmax, __shfl_xor_sync(0xFFFFFFFFu, lmax, o));
    }
    if ((threadIdx.x & 31) == 0) {
        atomicMin(&d_gminkey, fenc(lmin));
        atomicMax(&d_gmaxkey, fenc(lmax));
    }
}

// ---------------- 4) SpMM: 2 warps per row (column split), unroll 8 ---------
// Warp pair (r, half): half owns cols [half*32, half*32+32), lane = 1 fp32 col.
// Each warp stages exp(att)/ci for 32 edges into its smem slot, then sweeps
// with 8 gathers in flight. Row-sum computed redundantly per warp (no x-warp
// sync needed).
__global__ void __launch_bounds__(256) spmm_kernel(const int* __restrict__ ci,
                                                   float* __restrict__ out,
                                                   int nrows) {
    __shared__ float2 stage[8][32];
    int gid  = blockIdx.x * blockDim.x + threadIdx.x;
    int wg   = gid >> 5;
    int r    = wg >> 1;
    int half = wg & 1;
    int lane = gid & 31;
    int w    = (threadIdx.x >> 5);
    if (r >= nrows) return;

    const float mn = fdec(d_gminkey);
    const float sc = 1.0f / (fdec(d_gmaxkey) - mn);
    const int e0  = d_rowptr[r];
    const int end = d_rowptr[r + 1];

    const float* xp = d_Xp + half * 32 + lane;   // + c*64 per edge
    float ax = 0.f, s = 0.f;

    for (int b = e0; b < end; b += 32) {
        const int n = min(32, end - b);
        float a = 0.f;
        int   c = 0;
        if (lane < n) {
            a = __expf((d_att[b + lane] - mn) * sc);
            c = ci[b + lane];
        }
        s += a;
        stage[w][lane] = make_float2(a, __int_as_float(c));
        __syncwarp();

        int j = 0;
        for (; j + 7 < n; j += 8) {
            float2 t0 = stage[w][j];
            float2 t1 = stage[w][j + 1];
            float2 t2 = stage[w][j + 2];
            float2 t3 = stage[w][j + 3];
            float2 t4 = stage[w][j + 4];
            float2 t5 = stage[w][j + 5];
            float2 t6 = stage[w][j + 6];
            float2 t7 = stage[w][j + 7];
            float x0 = xp[(size_t)__float_as_int(t0.y) * 64];
            float x1 = xp[(size_t)__float_as_int(t1.y) * 64];
            float x2 = xp[(size_t)__float_as_int(t2.y) * 64];
            float x3 = xp[(size_t)__float_as_int(t3.y) * 64];
            float x4 = xp[(size_t)__float_as_int(t4.y) * 64];
            float x5 = xp[(size_t)__float_as_int(t5.y) * 64];
            float x6 = xp[(size_t)__float_as_int(t6.y) * 64];
            float x7 = xp[(size_t)__float_as_int(t7.y) * 64];
            ax += t0.x * x0 + t1.x * x1 + t2.x * x2 + t3.x * x3
                + t4.x * x4 + t5.x * x5 + t6.x * x6 + t7.x * x7;
        }
        for (; j < n; j++) {
            float2 tj = stage[w][j];
            ax += tj.x * xp[(size_t)__float_as_int(tj.y) * 64];
        }
        __syncwarp();
    }
#pragma unroll
    for (int o = 16; o; o >>= 1)
        s += __shfl_xor_sync(0xFFFFFFFFu, s, o);

    float inv = 1.0f / fmaxf(s, 1e-12f);
    out[(size_t)r * DOUT + half * 32 + lane] = ax * inv;
}

// ---------------- launch ---------------------------------------------------
extern "C" void kernel_launch(void* const* d_in, const int* in_sizes, int n_in,
                              void* d_out, int out_size) {
    const float* X  = (const float*)d_in[0];
    const float* W  = (const float*)d_in[1];
    const float* a0 = (const float*)d_in[2];
    const float* a1 = (const float*)d_in[3];
    const int*   ri = (const int*)d_in[4];
    const int*   ci = (const int*)d_in[5];
    float*       out = (float*)d_out;

    const int n = out_size / DOUT;   // 100000
    const int e = in_sizes[4];       // 1600000

    rowptr_kernel<<<(n + 1 + 255) / 256, 256>>>(ri, n, e);
    gemm_mma_kernel<<<(n + 255) / 256, 256>>>(X, W, a0, a1, n);
    const int ne8 = e >> 3, tail = e - ne8 * 8;
    edge_kernel<<<(ne8 + tail + 255) / 256, 256>>>(ri, ci, e);
    spmm_kernel<<<(n * 2 * 32 + 255) / 256, 256>>>(ci, out, n);
}

// round 10
// speedup vs baseline: 1.2200x; 1.2200x over previous
#include <cuda_runtime.h>
#include <cuda_fp16.h>
#include <cstdint>

#define NN     100000
#define EE     1600000
#define DIN    256
#define DOUT   64
#define ALPHA  0.2f

// ---------------- scratch ---------------------------------------------------
__device__ __half2 d_Xp16[(size_t)NN * 32];    // 12.8 MB  X @ W (fp16 col pairs)
__device__ float d_s0[NN];
__device__ float d_s1[NN];
__device__ float d_att[EE];                    // leakyrelu'd scores (pre-exp)
__device__ int   d_rowptr[NN + 1];
__device__ unsigned int d_gminkey;             // monotone-encoded float min
__device__ unsigned int d_gmaxkey;

// ---------------- monotone float<->uint encode ------------------------------
__device__ __forceinline__ unsigned int fenc(float f) {
    unsigned int u = __float_as_uint(f);
    return u ^ ((unsigned int)((int)u >> 31) | 0x80000000u);
}
__device__ __forceinline__ float fdec(unsigned int k) {
    unsigned int u = k ^ ((unsigned int)((int)(~k) >> 31) | 0x80000000u);
    return __uint_as_float(u);
}

// ---------------- fp16 helpers ----------------------------------------------
__device__ __forceinline__ uint32_t packh2(float a, float b) {
    __half2 h = __floats2half2_rn(a, b);      // a -> low half
    return *(uint32_t*)&h;
}

// mma.sync m16n8k16 fp16: D += A * B (A row-major 16x16, B col-major 16x8)
__device__ __forceinline__ void mma_fp16(float* d,
                                         uint32_t a0, uint32_t a1,
                                         uint32_t a2, uint32_t a3,
                                         uint32_t b0, uint32_t b1) {
    asm volatile(
        "mma.sync.aligned.m16n8k16.row.col.f32.f16.f16.f32 "
        "{%0,%1,%2,%3}, {%4,%5,%6,%7}, {%8,%9}, {%0,%1,%2,%3};"
        : "+f"(d[0]), "+f"(d[1]), "+f"(d[2]), "+f"(d[3])
        : "r"(a0), "r"(a1), "r"(a2), "r"(a3), "r"(b0), "r"(b1));
}

// ---------------- 1) fp16 single-pass tensor GEMM + fused scores ------------
#define BST2 132   // uint32 words per n-col (128 kpairs + 4 pad)

__global__ void __launch_bounds__(256, 2)
gemm_mma_kernel(const float* __restrict__ X, const float* __restrict__ W,
                const float* __restrict__ va0, const float* __restrict__ va1,
                int nrows) {
    __shared__ uint32_t Bs[DOUT * BST2];      // 33.8 KB  W^T fp16x2, full K

    const int tid  = threadIdx.x;
    const int wid  = tid >> 5;
    const int lane = tid & 31;
    const int g    = lane >> 2;
    const int t    = lane & 3;

    for (int idx = tid; idx < DOUT * (DIN / 2); idx += 256) {
        int n  = idx & 63;
        int kp = idx >> 6;
        int k  = kp * 2;
        Bs[n * BST2 + kp] = packh2(W[(size_t)k * DOUT + n],
                                   W[(size_t)(k + 1) * DOUT + n]);
    }

    const int m0 = blockIdx.x * 256 + wid * 32;
    const int r0 = m0 + g, r1 = m0 + g + 8, r2 = m0 + g + 16, r3 = m0 + g + 24;
    const bool v0 = r0 < nrows, v1 = r1 < nrows, v2 = r2 < nrows, v3 = r3 < nrows;
    const float* x0 = X + (size_t)r0 * DIN;
    const float* x1 = X + (size_t)r1 * DIN;
    const float* x2 = X + (size_t)r2 * DIN;
    const float* x3 = X + (size_t)r3 * DIN;

    float acc[2][8][4];
#pragma unroll
    for (int mt = 0; mt < 2; mt++)
#pragma unroll
        for (int nt = 0; nt < 8; nt++)
#pragma unroll
            for (int q = 0; q < 4; q++) acc[mt][nt][q] = 0.f;

    auto loadA = [&](float2* d, int s) {
        const int ks = s * 16;
        d[0] = v0 ? *(const float2*)(x0 + ks + 2 * t)     : make_float2(0.f, 0.f);
        d[1] = v1 ? *(const float2*)(x1 + ks + 2 * t)     : make_float2(0.f, 0.f);
        d[2] = v0 ? *(const float2*)(x0 + ks + 2 * t + 8) : make_float2(0.f, 0.f);
        d[3] = v1 ? *(const float2*)(x1 + ks + 2 * t + 8) : make_float2(0.f, 0.f);
        d[4] = v2 ? *(const float2*)(x2 + ks + 2 * t)     : make_float2(0.f, 0.f);
        d[5] = v3 ? *(const float2*)(x3 + ks + 2 * t)     : make_float2(0.f, 0.f);
        d[6] = v2 ? *(const float2*)(x2 + ks + 2 * t + 8) : make_float2(0.f, 0.f);
        d[7] = v3 ? *(const float2*)(x3 + ks + 2 * t + 8) : make_float2(0.f, 0.f);
    };
    auto compute = [&](const float2* d, int s) {
        uint32_t ah[2][4];
#pragma unroll
        for (int i = 0; i < 8; i++)
            ah[i >> 2][i & 3] = packh2(d[i].x, d[i].y);
        const int kp0 = s * 8;
#pragma unroll
        for (int nt = 0; nt < 8; nt++) {
            const int nb = (nt * 8 + g) * BST2 + kp0 + t;
            uint32_t b0 = Bs[nb], b1 = Bs[nb + 4];
#pragma unroll
            for (int mt = 0; mt < 2; mt++)
                mma_fp16(acc[mt][nt], ah[mt][0], ah[mt][1], ah[mt][2], ah[mt][3], b0, b1);
        }
    };

    float2 bufA[8], bufB[8];
    loadA(bufA, 0);
    __syncthreads();          // B smem ready

#pragma unroll 1
    for (int s = 0; s < 16; s += 2) {
        if (s + 1 < 16) loadA(bufB, s + 1);
        compute(bufA, s);
        if (s + 2 < 16) loadA(bufA, s + 2);
        if (s + 1 < 16) compute(bufB, s + 1);
    }

    // ---- epilogue: fp16 Xp store + fused s0/s1 ----
    float p0[2][2] = {{0.f, 0.f}, {0.f, 0.f}};
    float p1[2][2] = {{0.f, 0.f}, {0.f, 0.f}};
#pragma unroll
    for (int nt = 0; nt < 8; nt++) {
        float2 c0 = *(const float2*)&va0[nt * 8 + t * 2];
        float2 c1 = *(const float2*)&va1[nt * 8 + t * 2];
#pragma unroll
        for (int mt = 0; mt < 2; mt++) {
            p0[mt][0] += acc[mt][nt][0] * c0.x + acc[mt][nt][1] * c0.y;
            p0[mt][1] += acc[mt][nt][2] * c0.x + acc[mt][nt][3] * c0.y;
            p1[mt][0] += acc[mt][nt][0] * c1.x + acc[mt][nt][1] * c1.y;
            p1[mt][1] += acc[mt][nt][2] * c1.x + acc[mt][nt][3] * c1.y;
        }
    }
#pragma unroll
    for (int mt = 0; mt < 2; mt++)
#pragma unroll
        for (int hb = 0; hb < 2; hb++) {
            p0[mt][hb] += __shfl_xor_sync(0xFFFFFFFFu, p0[mt][hb], 1);
            p0[mt][hb] += __shfl_xor_sync(0xFFFFFFFFu, p0[mt][hb], 2);
            p1[mt][hb] += __shfl_xor_sync(0xFFFFFFFFu, p1[mt][hb], 1);
            p1[mt][hb] += __shfl_xor_sync(0xFFFFFFFFu, p1[mt][hb], 2);
        }

#pragma unroll
    for (int mt = 0; mt < 2; mt++) {
        int rowA = m0 + mt * 16 + g;
        int rowB = rowA + 8;
#pragma unroll
        for (int nt = 0; nt < 8; nt++) {
            int cp = nt * 4 + t;     // col-pair index (cols 2cp, 2cp+1)
            if (rowA < nrows)
                d_Xp16[(size_t)rowA * 32 + cp] =
                    __floats2half2_rn(acc[mt][nt][0], acc[mt][nt][1]);
            if (rowB < nrows)
                d_Xp16[(size_t)rowB * 32 + cp] =
                    __floats2half2_rn(acc[mt][nt][2], acc[mt][nt][3]);
        }
        if (t == 0) {
            if (rowA < nrows) { d_s0[rowA] = p0[mt][0]; d_s1[rowA] = p1[mt][0]; }
            if (rowB < nrows) { d_s0[rowB] = p0[mt][1]; d_s1[rowB] = p1[mt][1]; }
        }
    }
}

// ---------------- 2) row_ptr from sorted row_index + key init ---------------
__global__ void rowptr_kernel(const int* __restrict__ ri, int nrows, int ne) {
    if (blockIdx.x == 0 && threadIdx.x == 0) {
        d_gminkey = 0xFFFFFFFFu;
        d_gmaxkey = 0u;
    }
    int r = blockIdx.x * blockDim.x + threadIdx.x;
    if (r > nrows) return;
    int lo = 0, hi = ne;
    while (lo < hi) {
        int mid = (lo + hi) >> 1;
        if (ri[mid] < r) lo = mid + 1; else hi = mid;
    }
    d_rowptr[r] = lo;
}

// ---------------- 3) SDDMM + LeakyReLU + atomic min/max (8 edges/thread) ----
__global__ void __launch_bounds__(256) edge_kernel(const int* __restrict__ ri,
                                                   const int* __restrict__ ci,
                                                   int ne) {
    const int ne8  = ne >> 3;
    const int tail = ne - ne8 * 8;
    const int i    = blockIdx.x * blockDim.x + threadIdx.x;

    float lmin = 3.4e38f, lmax = -3.4e38f;
    if (i < ne8) {
        int4 ra = *(const int4*)&ri[(size_t)i * 8];
        int4 rb = *(const int4*)&ri[(size_t)i * 8 + 4];
        int4 ca = *(const int4*)&ci[(size_t)i * 8];
        int4 cb = *(const int4*)&ci[(size_t)i * 8 + 4];
        float v0 = d_s0[ra.x] + d_s1[ca.x];
        float v1 = d_s0[ra.y] + d_s1[ca.y];
        float v2 = d_s0[ra.z] + d_s1[ca.z];
        float v3 = d_s0[ra.w] + d_s1[ca.w];
        float v4 = d_s0[rb.x] + d_s1[cb.x];
        float v5 = d_s0[rb.y] + d_s1[cb.y];
        float v6 = d_s0[rb.z] + d_s1[cb.z];
        float v7 = d_s0[rb.w] + d_s1[cb.w];
        v0 = v0 > 0.f ? v0 : ALPHA * v0;
        v1 = v1 > 0.f ? v1 : ALPHA * v1;
        v2 = v2 > 0.f ? v2 : ALPHA * v2;
        v3 = v3 > 0.f ? v3 : ALPHA * v3;
        v4 = v4 > 0.f ? v4 : ALPHA * v4;
        v5 = v5 > 0.f ? v5 : ALPHA * v5;
        v6 = v6 > 0.f ? v6 : ALPHA * v6;
        v7 = v7 > 0.f ? v7 : ALPHA * v7;
        *(float4*)&d_att[(size_t)i * 8]     = make_float4(v0, v1, v2, v3);
        *(float4*)&d_att[(size_t)i * 8 + 4] = make_float4(v4, v5, v6, v7);
        lmin = fminf(fminf(fminf(v0, v1), fminf(v2, v3)),
                     fminf(fminf(v4, v5), fminf(v6, v7)));
        lmax = fmaxf(fmaxf(fmaxf(v0, v1), fmaxf(v2, v3)),
                     fmaxf(fmaxf(v4, v5), fmaxf(v6, v7)));
    } else if (i - ne8 < tail) {
        int e = ne8 * 8 + (i - ne8);
        float v = d_s0[ri[e]] + d_s1[ci[e]];
        v = v > 0.f ? v : ALPHA * v;
        d_att[e] = v;
        lmin = v; lmax = v;
    }
#pragma unroll
    for (int o = 16; o; o >>= 1) {
        lmin = fminf(lmin, __shfl_xor_sync(0xFFFFFFFFu, lmin, o));
        lmax = fmaxf(lmax, __shfl_xor_sync(0xFFFFFFFFu, lmax, o));
    }
    if ((threadIdx.x & 31) == 0) {
        atomicMin(&d_gminkey, fenc(lmin));
        atomicMax(&d_gmaxkey, fenc(lmax));
    }
}

// ---------------- 4) SpMM: smem-staged (a,c) + fp16 gather ------------------
// Warp per row. Lanes batch exp(att)/ci for 32 edges into smem; all lanes
// sweep staged pairs (LDS.64 broadcast); lane owns 2 cols via one half2
// (gather = 128B/row = 1 L1 line = 1 wavefront per edge).
__global__ void __launch_bounds__(256) spmm_kernel(const int* __restrict__ ci,
                                                   float* __restrict__ out,
                                                   int nrows) {
    __shared__ float2 stage[8][32];
    int gid  = blockIdx.x * blockDim.x + threadIdx.x;
    int r    = gid >> 5;
    int lane = gid & 31;
    int w    = (threadIdx.x >> 5);
    if (r >= nrows) return;

    const float mn = fdec(d_gminkey);
    const float sc = 1.0f / (fdec(d_gmaxkey) - mn);
    const int e0  = d_rowptr[r];
    const int end = d_rowptr[r + 1];

    const __half2* xp = d_Xp16 + lane;   // + c*32 per edge
    float ax = 0.f, ay = 0.f, s = 0.f;

    for (int b = e0; b < end; b += 32) {
        const int n = min(32, end - b);
        float a = 0.f;
        int   c = 0;
        if (lane < n) {
            a = __expf((d_att[b + lane] - mn) * sc);
            c = ci[b + lane];
        }
        s += a;
        stage[w][lane] = make_float2(a, __int_as_float(c));
        __syncwarp();

        int j = 0;
        for (; j + 3 < n; j += 4) {
            float2 t0 = stage[w][j];
            float2 t1 = stage[w][j + 1];
            float2 t2 = stage[w][j + 2];
            float2 t3 = stage[w][j + 3];
            float2 x0 = __half22float2(xp[(size_t)__float_as_int(t0.y) * 32]);
            float2 x1 = __half22float2(xp[(size_t)__float_as_int(t1.y) * 32]);
            float2 x2 = __half22float2(xp[(size_t)__float_as_int(t2.y) * 32]);
            float2 x3 = __half22float2(xp[(size_t)__float_as_int(t3.y) * 32]);
            ax += t0.x * x0.x + t1.x * x1.x + t2.x * x2.x + t3.x * x3.x;
            ay += t0.x * x0.y + t1.x * x1.y + t2.x * x2.y + t3.x * x3.y;
        }
        for (; j < n; j++) {
            float2 tj = stage[w][j];
            float2 x  = __half22float2(xp[(size_t)__float_as_int(tj.y) * 32]);
            ax += tj.x * x.x;
            ay += tj.x * x.y;
        }
        __syncwarp();
    }
#pragma unroll
    for (int o = 16; o; o >>= 1)
        s += __shfl_xor_sync(0xFFFFFFFFu, s, o);

    float inv = 1.0f / fmaxf(s, 1e-12f);
    *(float2*)&out[(size_t)r * DOUT + lane * 2] = make_float2(ax * inv, ay * inv);
}

// ---------------- launch ---------------------------------------------------
extern "C" void kernel_launch(void* const* d_in, const int* in_sizes, int n_in,
                              void* d_out, int out_size) {
    const float* X  = (const float*)d_in[0];
    const float* W  = (const float*)d_in[1];
    const float* a0 = (const float*)d_in[2];
    const float* a1 = (const float*)d_in[3];
    const int*   ri = (const int*)d_in[4];
    const int*   ci = (const int*)d_in[5];
    float*       out = (float*)d_out;

    const int n = out_size / DOUT;   // 100000
    const int e = in_sizes[4];       // 1600000

    rowptr_kernel<<<(n + 1 + 255) / 256, 256>>>(ri, n, e);
    gemm_mma_kernel<<<(n + 255) / 256, 256>>>(X, W, a0, a1, n);
    const int ne8 = e >> 3, tail = e - ne8 * 8;
    edge_kernel<<<(ne8 + tail + 255) / 256, 256>>>(ri, ci, e);
    spmm_kernel<<<(n * 32 + 255) / 256, 256>>>(ci, out, n);
}

// round 12
// speedup vs baseline: 1.2731x; 1.0436x over previous
#include <cuda_runtime.h>
#include <cuda_fp16.h>
#include <cstdint>

#define NN     100000
#define EE     1600000
#define DIN    256
#define DOUT   64
#define ALPHA  0.2f

// ---------------- scratch ---------------------------------------------------
__device__ __half2 d_Xp16[(size_t)NN * 32];    // 12.8 MB  X @ W (fp16 col pairs)
__device__ float d_s0[NN];
__device__ float d_s1[NN];
__device__ float d_att[EE];                    // leakyrelu'd scores (pre-exp)
__device__ int   d_rowptr[NN + 1];
__device__ unsigned int d_gminkey;             // monotone-encoded float min
__device__ unsigned int d_gmaxkey;

// ---------------- monotone float<->uint encode ------------------------------
__device__ __forceinline__ unsigned int fenc(float f) {
    unsigned int u = __float_as_uint(f);
    return u ^ ((unsigned int)((int)u >> 31) | 0x80000000u);
}
__device__ __forceinline__ float fdec(unsigned int k) {
    unsigned int u = k ^ ((unsigned int)((int)(~k) >> 31) | 0x80000000u);
    return __uint_as_float(u);
}

// ---------------- fp16 helpers ----------------------------------------------
__device__ __forceinline__ uint32_t packh2(float a, float b) {
    __half2 h = __floats2half2_rn(a, b);      // a -> low half
    return *(uint32_t*)&h;
}

// mma.sync m16n8k16 fp16: D += A * B (A row-major 16x16, B col-major 16x8)
__device__ __forceinline__ void mma_fp16(float* d,
                                         uint32_t a0, uint32_t a1,
                                         uint32_t a2, uint32_t a3,
                                         uint32_t b0, uint32_t b1) {
    asm volatile(
        "mma.sync.aligned.m16n8k16.row.col.f32.f16.f16.f32 "
        "{%0,%1,%2,%3}, {%4,%5,%6,%7}, {%8,%9}, {%0,%1,%2,%3};"
        : "+f"(d[0]), "+f"(d[1]), "+f"(d[2]), "+f"(d[3])
        : "r"(a0), "r"(a1), "r"(a2), "r"(a3), "r"(b0), "r"(b1));
}

// ---------------- 1) fp16 single-pass tensor GEMM + fused scores ------------
#define BST2 132   // uint32 words per n-col (128 kpairs + 4 pad)

__global__ void __launch_bounds__(256, 2)
gemm_mma_kernel(const float* __restrict__ X, const float* __restrict__ W,
                const float* __restrict__ va0, const float* __restrict__ va1,
                int nrows) {
    __shared__ uint32_t Bs[DOUT * BST2];      // 33.8 KB  W^T fp16x2, full K

    const int tid  = threadIdx.x;
    const int wid  = tid >> 5;
    const int lane = tid & 31;
    const int g    = lane >> 2;
    const int t    = lane & 3;

    for (int idx = tid; idx < DOUT * (DIN / 2); idx += 256) {
        int n  = idx & 63;
        int kp = idx >> 6;
        int k  = kp * 2;
        Bs[n * BST2 + kp] = packh2(W[(size_t)k * DOUT + n],
                                   W[(size_t)(k + 1) * DOUT + n]);
    }

    const int m0 = blockIdx.x * 256 + wid * 32;
    const int r0 = m0 + g, r1 = m0 + g + 8, r2 = m0 + g + 16, r3 = m0 + g + 24;
    const bool v0 = r0 < nrows, v1 = r1 < nrows, v2 = r2 < nrows, v3 = r3 < nrows;
    const float* x0 = X + (size_t)r0 * DIN;
    const float* x1 = X + (size_t)r1 * DIN;
    const float* x2 = X + (size_t)r2 * DIN;
    const float* x3 = X + (size_t)r3 * DIN;

    float acc[2][8][4];
#pragma unroll
    for (int mt = 0; mt < 2; mt++)
#pragma unroll
        for (int nt = 0; nt < 8; nt++)
#pragma unroll
            for (int q = 0; q < 4; q++) acc[mt][nt][q] = 0.f;

    auto loadA = [&](float2* d, int s) {
        const int ks = s * 16;
        d[0] = v0 ? *(const float2*)(x0 + ks + 2 * t)     : make_float2(0.f, 0.f);
        d[1] = v1 ? *(const float2*)(x1 + ks + 2 * t)     : make_float2(0.f, 0.f);
        d[2] = v0 ? *(const float2*)(x0 + ks + 2 * t + 8) : make_float2(0.f, 0.f);
        d[3] = v1 ? *(const float2*)(x1 + ks + 2 * t + 8) : make_float2(0.f, 0.f);
        d[4] = v2 ? *(const float2*)(x2 + ks + 2 * t)     : make_float2(0.f, 0.f);
        d[5] = v3 ? *(const float2*)(x3 + ks + 2 * t)     : make_float2(0.f, 0.f);
        d[6] = v2 ? *(const float2*)(x2 + ks + 2 * t + 8) : make_float2(0.f, 0.f);
        d[7] = v3 ? *(const float2*)(x3 + ks + 2 * t + 8) : make_float2(0.f, 0.f);
    };
    auto compute = [&](const float2* d, int s) {
        uint32_t ah[2][4];
#pragma unroll
        for (int i = 0; i < 8; i++)
            ah[i >> 2][i & 3] = packh2(d[i].x, d[i].y);
        const int kp0 = s * 8;
#pragma unroll
        for (int nt = 0; nt < 8; nt++) {
            const int nb = (nt * 8 + g) * BST2 + kp0 + t;
            uint32_t b0 = Bs[nb], b1 = Bs[nb + 4];
#pragma unroll
            for (int mt = 0; mt < 2; mt++)
                mma_fp16(acc[mt][nt], ah[mt][0], ah[mt][1], ah[mt][2], ah[mt][3], b0, b1);
        }
    };

    float2 bufA[8], bufB[8];
    loadA(bufA, 0);
    __syncthreads();          // B smem ready

#pragma unroll 1
    for (int s = 0; s < 16; s += 2) {
        if (s + 1 < 16) loadA(bufB, s + 1);
        compute(bufA, s);
        if (s + 2 < 16) loadA(bufA, s + 2);
        if (s + 1 < 16) compute(bufB, s + 1);
    }

    // ---- epilogue: fp16 Xp store + fused s0/s1 ----
    float p0[2][2] = {{0.f, 0.f}, {0.f, 0.f}};
    float p1[2][2] = {{0.f, 0.f}, {0.f, 0.f}};
#pragma unroll
    for (int nt = 0; nt < 8; nt++) {
        float2 c0 = *(const float2*)&va0[nt * 8 + t * 2];
        float2 c1 = *(const float2*)&va1[nt * 8 + t * 2];
#pragma unroll
        for (int mt = 0; mt < 2; mt++) {
            p0[mt][0] += acc[mt][nt][0] * c0.x + acc[mt][nt][1] * c0.y;
            p0[mt][1] += acc[mt][nt][2] * c0.x + acc[mt][nt][3] * c0.y;
            p1[mt][0] += acc[mt][nt][0] * c1.x + acc[mt][nt][1] * c1.y;
            p1[mt][1] += acc[mt][nt][2] * c1.x + acc[mt][nt][3] * c1.y;
        }
    }
#pragma unroll
    for (int mt = 0; mt < 2; mt++)
#pragma unroll
        for (int hb = 0; hb < 2; hb++) {
            p0[mt][hb] += __shfl_xor_sync(0xFFFFFFFFu, p0[mt][hb], 1);
            p0[mt][hb] += __shfl_xor_sync(0xFFFFFFFFu, p0[mt][hb], 2);
            p1[mt][hb] += __shfl_xor_sync(0xFFFFFFFFu, p1[mt][hb], 1);
            p1[mt][hb] += __shfl_xor_sync(0xFFFFFFFFu, p1[mt][hb], 2);
        }

#pragma unroll
    for (int mt = 0; mt < 2; mt++) {
        int rowA = m0 + mt * 16 + g;
        int rowB = rowA + 8;
#pragma unroll
        for (int nt = 0; nt < 8; nt++) {
            int cp = nt * 4 + t;     // col-pair index (cols 2cp, 2cp+1)
            if (rowA < nrows)
                d_Xp16[(size_t)rowA * 32 + cp] =
                    __floats2half2_rn(acc[mt][nt][0], acc[mt][nt][1]);
            if (rowB < nrows)
                d_Xp16[(size_t)rowB * 32 + cp] =
                    __floats2half2_rn(acc[mt][nt][2], acc[mt][nt][3]);
        }
        if (t == 0) {
            if (rowA < nrows) { d_s0[rowA] = p0[mt][0]; d_s1[rowA] = p1[mt][0]; }
            if (rowB < nrows) { d_s0[rowB] = p0[mt][1]; d_s1[rowB] = p1[mt][1]; }
        }
    }
}

// ---------------- 2) row_ptr from sorted row_index + key init ---------------
__global__ void rowptr_kernel(const int* __restrict__ ri, int nrows, int ne) {
    if (blockIdx.x == 0 && threadIdx.x == 0) {
        d_gminkey = 0xFFFFFFFFu;
        d_gmaxkey = 0u;
    }
    int r = blockIdx.x * blockDim.x + threadIdx.x;
    if (r > nrows) return;
    int lo = 0, hi = ne;
    while (lo < hi) {
        int mid = (lo + hi) >> 1;
        if (ri[mid] < r) lo = mid + 1; else hi = mid;
    }
    d_rowptr[r] = lo;
}

// ---------------- 3) SDDMM + LeakyReLU + atomic min/max (8 edges/thread) ----
__global__ void __launch_bounds__(256) edge_kernel(const int* __restrict__ ri,
                                                   const int* __restrict__ ci,
                                                   int ne) {
    const int ne8  = ne >> 3;
    const int tail = ne - ne8 * 8;
    const int i    = blockIdx.x * blockDim.x + threadIdx.x;

    float lmin = 3.4e38f, lmax = -3.4e38f;
    if (i < ne8) {
        int4 ra = *(const int4*)&ri[(size_t)i * 8];
        int4 rb = *(const int4*)&ri[(size_t)i * 8 + 4];
        int4 ca = *(const int4*)&ci[(size_t)i * 8];
        int4 cb = *(const int4*)&ci[(size_t)i * 8 + 4];
        float v0 = d_s0[ra.x] + d_s1[ca.x];
        float v1 = d_s0[ra.y] + d_s1[ca.y];
        float v2 = d_s0[ra.z] + d_s1[ca.z];
        float v3 = d_s0[ra.w] + d_s1[ca.w];
        float v4 = d_s0[rb.x] + d_s1[cb.x];
        float v5 = d_s0[rb.y] + d_s1[cb.y];
        float v6 = d_s0[rb.z] + d_s1[cb.z];
        float v7 = d_s0[rb.w] + d_s1[cb.w];
        v0 = v0 > 0.f ? v0 : ALPHA * v0;
        v1 = v1 > 0.f ? v1 : ALPHA * v1;
        v2 = v2 > 0.f ? v2 : ALPHA * v2;
        v3 = v3 > 0.f ? v3 : ALPHA * v3;
        v4 = v4 > 0.f ? v4 : ALPHA * v4;
        v5 = v5 > 0.f ? v5 : ALPHA * v5;
        v6 = v6 > 0.f ? v6 : ALPHA * v6;
        v7 = v7 > 0.f ? v7 : ALPHA * v7;
        *(float4*)&d_att[(size_t)i * 8]     = make_float4(v0, v1, v2, v3);
        *(float4*)&d_att[(size_t)i * 8 + 4] = make_float4(v4, v5, v6, v7);
        lmin = fminf(fminf(fminf(v0, v1), fminf(v2, v3)),
                     fminf(fminf(v4, v5), fminf(v6, v7)));
        lmax = fmaxf(fmaxf(fmaxf(v0, v1), fmaxf(v2, v3)),
                     fmaxf(fmaxf(v4, v5), fmaxf(v6, v7)));
    } else if (i - ne8 < tail) {
        int e = ne8 * 8 + (i - ne8);
        float v = d_s0[ri[e]] + d_s1[ci[e]];
        v = v > 0.f ? v : ALPHA * v;
        d_att[e] = v;
        lmin = v; lmax = v;
    }
#pragma unroll
    for (int o = 16; o; o >>= 1) {
        lmin = fminf(lmin, __shfl_xor_sync(0xFFFFFFFFu, lmin, o));
        lmax = fmaxf(lmax, __shfl_xor_sync(0xFFFFFFFFu, lmax, o));
    }
    if ((threadIdx.x & 31) == 0) {
        atomicMin(&d_gminkey, fenc(lmin));
        atomicMax(&d_gmaxkey, fenc(lmax));
    }
}

// ---------------- 4) SpMM: smem-staged (a,c) + fp16 gather, MLP 8 -----------
// Warp per row. Lanes batch exp(att)/ci for 32 edges into smem; all lanes
// sweep staged pairs (LDS.64 broadcast) with 8 gathers in flight; lane owns
// 2 cols via one half2 (gather = 128B/row = 1 L1 line/edge).
__global__ void __launch_bounds__(256) spmm_kernel(const int* __restrict__ ci,
                                                   float* __restrict__ out,
                                                   int nrows) {
    __shared__ float2 stage[8][32];
    int gid  = blockIdx.x * blockDim.x + threadIdx.x;
    int r    = gid >> 5;
    int lane = gid & 31;
    int w    = (threadIdx.x >> 5);
    if (r >= nrows) return;

    const float mn = fdec(d_gminkey);
    const float sc = 1.0f / (fdec(d_gmaxkey) - mn);
    const int e0  = d_rowptr[r];
    const int end = d_rowptr[r + 1];

    const __half2* xp = d_Xp16 + lane;   // + c*32 per edge
    float ax = 0.f, ay = 0.f, s = 0.f;

    for (int b = e0; b < end; b += 32) {
        const int n = min(32, end - b);
        float a = 0.f;
        int   c = 0;
        if (lane < n) {
            a = __expf((d_att[b + lane] - mn) * sc);
            c = ci[b + lane];
        }
        s += a;
        stage[w][lane] = make_float2(a, __int_as_float(c));
        __syncwarp();

        int j = 0;
        for (; j + 7 < n; j += 8) {
            float2 t0 = stage[w][j];
            float2 t1 = stage[w][j + 1];
            float2 t2 = stage[w][j + 2];
            float2 t3 = stage[w][j + 3];
            float2 t4 = stage[w][j + 4];
            float2 t5 = stage[w][j + 5];
            float2 t6 = stage[w][j + 6];
            float2 t7 = stage[w][j + 7];
            __half2 h0 = xp[(size_t)__float_as_int(t0.y) * 32];
            __half2 h1 = xp[(size_t)__float_as_int(t1.y) * 32];
            __half2 h2 = xp[(size_t)__float_as_int(t2.y) * 32];
            __half2 h3 = xp[(size_t)__float_as_int(t3.y) * 32];
            __half2 h4 = xp[(size_t)__float_as_int(t4.y) * 32];
            __half2 h5 = xp[(size_t)__float_as_int(t5.y) * 32];
            __half2 h6 = xp[(size_t)__float_as_int(t6.y) * 32];
            __half2 h7 = xp[(size_t)__float_as_int(t7.y) * 32];
            float2 x0 = __half22float2(h0);
            float2 x1 = __half22float2(h1);
            float2 x2 = __half22float2(h2);
            float2 x3 = __half22float2(h3);
            float2 x4 = __half22float2(h4);
            float2 x5 = __half22float2(h5);
            float2 x6 = __half22float2(h6);
            float2 x7 = __half22float2(h7);
            ax += t0.x * x0.x + t1.x * x1.x + t2.x * x2.x + t3.x * x3.x
                + t4.x * x4.x + t5.x * x5.x + t6.x * x6.x + t7.x * x7.x;
            ay += t0.x * x0.y + t1.x * x1.y + t2.x * x2.y + t3.x * x3.y
                + t4.x * x4.y + t5.x * x5.y + t6.x * x6.y + t7.x * x7.y;
        }
        for (; j + 3 < n; j += 4) {
            float2 t0 = stage[w][j];
            float2 t1 = stage[w][j + 1];
            float2 t2 = stage[w][j + 2];
            float2 t3 = stage[w][j + 3];
            float2 x0 = __half22float2(xp[(size_t)__float_as_int(t0.y) * 32]);
            float2 x1 = __half22float2(xp[(size_t)__float_as_int(t1.y) * 32]);
            float2 x2 = __half22float2(xp[(size_t)__float_as_int(t2.y) * 32]);
            float2 x3 = __half22float2(xp[(size_t)__float_as_int(t3.y) * 32]);
            ax += t0.x * x0.x + t1.x * x1.x + t2.x * x2.x + t3.x * x3.x;
            ay += t0.x * x0.y + t1.x * x1.y + t2.x * x2.y + t3.x * x3.y;
        }
        for (; j < n; j++) {
            float2 tj = stage[w][j];
            float2 x  = __half22float2(xp[(size_t)__float_as_int(tj.y) * 32]);
            ax += tj.x * x.x;
            ay += tj.x * x.y;
        }
        __syncwarp();
    }
#pragma unroll
    for (int o = 16; o; o >>= 1)
        s += __shfl_xor_sync(0xFFFFFFFFu, s, o);

    float inv = 1.0f / fmaxf(s, 1e-12f);
    *(float2*)&out[(size_t)r * DOUT + lane * 2] = make_float2(ax * inv, ay * inv);
}

// ---------------- launch ---------------------------------------------------
extern "C" void kernel_launch(void* const* d_in, const int* in_sizes, int n_in,
                              void* d_out, int out_size) {
    const float* X  = (const float*)d_in[0];
    const float* W  = (const float*)d_in[1];
    const float* a0 = (const float*)d_in[2];
    const float* a1 = (const float*)d_in[3];
    const int*   ri = (const int*)d_in[4];
    const int*   ci = (const int*)d_in[5];
    float*       out = (float*)d_out;

    const int n = out_size / DOUT;   // 100000
    const int e = in_sizes[4];       // 1600000

    rowptr_kernel<<<(n + 1 + 255) / 256, 256>>>(ri, n, e);
    gemm_mma_kernel<<<(n + 255) / 256, 256>>>(X, W, a0, a1, n);
    const int ne8 = e >> 3, tail = e - ne8 * 8;
    edge_kernel<<<(ne8 + tail + 255) / 256, 256>>>(ri, ci, e);
    spmm_kernel<<<(n * 32 + 255) / 256, 256>>>(ci, out, n);
}